// round 6
// baseline (speedup 1.0000x reference)
#include <cuda_runtime.h>

// Problem constants
#define MAXN 100000
#define MAXE 1600000
#define FIN 64
#define HID 64
#define NCLS 32

// ---------------- scratch (static device globals; no allocation) -------------
__device__ int   g_is64;
__device__ int   g_deg[MAXN];
__device__ int   g_rowptr[MAXN + 1];
__device__ int   g_cursor[MAXN];
__device__ float g_dinv[MAXN];
__device__ int   g_csrcol[MAXE];
__device__ float g_csrw[MAXE];
__device__ float g_bufA[MAXN * 64];
__device__ float g_bufB[MAXN * 64];
__device__ float g_bufC[MAXN * 64];

// resolve scratch-buffer selector inside device code (no host symbol lookup)
__device__ __forceinline__ float* selbuf(int s) {
    return (s == 0) ? g_bufA : (s == 1) ? g_bufB : g_bufC;
}

// read edge-index element e (element space of the TRUE dtype)
__device__ __forceinline__ int edge_at(const void* ei, int e) {
    if (g_is64) return (int)((const long long*)ei)[e];
    return ((const int*)ei)[e];
}

// ---------------- threefry2x32 (20 rounds) -----------------------------------
__device__ __forceinline__ unsigned rotl32(unsigned x, int d) {
    return (x << d) | (x >> (32 - d));
}

__device__ __forceinline__ void tf20(unsigned k0, unsigned k1,
                                     unsigned c0, unsigned c1,
                                     unsigned& o0, unsigned& o1) {
    unsigned ks0 = k0, ks1 = k1, ks2 = 0x1BD11BDAu ^ k0 ^ k1;
    unsigned x0 = c0 + ks0, x1 = c1 + ks1;
#define TFR(r) { x0 += x1; x1 = rotl32(x1, (r)); x1 ^= x0; }
    TFR(13) TFR(15) TFR(26) TFR(6)
    x0 += ks1; x1 += ks2 + 1u;
    TFR(17) TFR(29) TFR(16) TFR(24)
    x0 += ks2; x1 += ks0 + 2u;
    TFR(13) TFR(15) TFR(26) TFR(6)
    x0 += ks0; x1 += ks1 + 3u;
    TFR(17) TFR(29) TFR(16) TFR(24)
    x0 += ks1; x1 += ks2 + 4u;
    TFR(13) TFR(15) TFR(26) TFR(6)
    x0 += ks2; x1 += ks0 + 5u;
#undef TFR
    o0 = x0; o1 = x1;
}

__device__ __forceinline__ float tf_uniform(unsigned bits) {
    return __uint_as_float((bits >> 9) | 0x3F800000u) - 1.0f;
}

// ---------------- dtype probe -------------------------------------------------
__global__ void detect_kernel(const unsigned* __restrict__ w) {
    if (threadIdx.x == 0) {
        int is64 = 1;
        #pragma unroll
        for (int k = 0; k < 8; k++)
            if (w[2 * k + 1] != 0u) is64 = 0;
        g_is64 = is64;
    }
}

// ---------------- setup kernels ----------------------------------------------
__global__ void zero_deg_kernel(int n) {
    int i = blockIdx.x * blockDim.x + threadIdx.x;
    if (i < n) g_deg[i] = 0;
}

__global__ void deg_hist_kernel(const void* __restrict__ ei, int E) {
    int e = blockIdx.x * blockDim.x + threadIdx.x;
    if (e < E) {
        int r = edge_at(ei, e);
        atomicAdd(&g_deg[r], 1);
    }
}

__global__ void scan_kernel(int n) {
    __shared__ int partials[1024];
    int t = threadIdx.x;
    int chunk = (n + 1023) / 1024;
    int begin = t * chunk;
    int endi  = min(begin + chunk, n);
    int s = 0;
    for (int i = begin; i < endi; i++) s += g_deg[i];
    partials[t] = s;
    __syncthreads();
    for (int off = 1; off < 1024; off <<= 1) {
        int v = (t >= off) ? partials[t - off] : 0;
        __syncthreads();
        if (t >= off) partials[t] += v;
        __syncthreads();
    }
    int run = (t == 0) ? 0 : partials[t - 1];
    for (int i = begin; i < endi; i++) {
        g_rowptr[i] = run;
        g_cursor[i] = run;
        run += g_deg[i];
    }
    if (endi == n) g_rowptr[n] = run;
}

__global__ void dinv_kernel(int n) {
    int i = blockIdx.x * blockDim.x + threadIdx.x;
    if (i < n) {
        int d = g_deg[i];
        g_dinv[i] = (d > 0) ? rsqrtf((float)d) : 0.0f;
    }
}

__global__ void scatter_kernel(const void* __restrict__ ei, int E) {
    int e = blockIdx.x * blockDim.x + threadIdx.x;
    if (e < E) {
        int r = edge_at(ei, e);
        int c = edge_at(ei, E + e);
        int pos = atomicAdd(&g_cursor[r], 1);
        g_csrcol[pos] = c;
        g_csrw[pos]   = -(g_dinv[r] * g_dinv[c]);
    }
}

// ---------------- SpMM --------------------------------------------------------
__global__ void spmm_kernel(const float* __restrict__ ext_src, int src_sel,
                            int dst_sel,
                            const float* __restrict__ ext_other, int other_sel,
                            int mode, int n) {
    const float* src = (src_sel < 0) ? ext_src : selbuf(src_sel);
    float*       dst = selbuf(dst_sel);
    int warp = (blockIdx.x * blockDim.x + threadIdx.x) >> 5;
    int lane = threadIdx.x & 31;
    if (warp >= n) return;
    int start = g_rowptr[warp];
    int end   = g_rowptr[warp + 1];
    const float2* s2 = (const float2*)src;
    float ax = 0.f, ay = 0.f;
    int e = start;
    for (; e + 1 < end; e += 2) {
        int   c0 = g_csrcol[e];
        int   c1 = g_csrcol[e + 1];
        float w0 = g_csrw[e];
        float w1 = g_csrw[e + 1];
        float2 v0 = __ldg(&s2[c0 * 32 + lane]);
        float2 v1 = __ldg(&s2[c1 * 32 + lane]);
        ax += w0 * v0.x + w1 * v1.x;
        ay += w0 * v0.y + w1 * v1.y;
    }
    if (e < end) {
        int c = g_csrcol[e];
        float w = g_csrw[e];
        float2 v = __ldg(&s2[c * 32 + lane]);
        ax += w * v.x;
        ay += w * v.y;
    }
    if (mode) {
        const float* oth = (other_sel < 0) ? ext_other : selbuf(other_sel);
        float2 o = ((const float2*)oth)[warp * 32 + lane];
        ax = 2.0f * ax - o.x;
        ay = 2.0f * ay - o.y;
    }
    ((float2*)dst)[warp * 32 + lane] = make_float2(ax, ay);
}

// ---------------- GEMM1 -------------------------------------------------------
__global__ void gemm1_kernel(const float* __restrict__ x,
                             const float* __restrict__ W,
                             const float* __restrict__ b, int n) {
    __shared__ float sw[3 * 64 * 64];
    for (int i = threadIdx.x; i < 3 * 64 * 64 / 4; i += 256)
        ((float4*)sw)[i] = ((const float4*)W)[i];
    __syncthreads();

    int node = blockIdx.x * 64 + (threadIdx.x >> 2);
    int jb   = (threadIdx.x & 3) * 16;
    if (node >= n) return;

    float acc[16];
#pragma unroll
    for (int j = 0; j < 16; j++) acc[j] = __ldg(&b[jb + j]);

    const float* ins[3] = { x + node * 64, g_bufA + node * 64, g_bufB + node * 64 };
#pragma unroll
    for (int m = 0; m < 3; m++) {
        const float4* ip = (const float4*)ins[m];
        const float* wm = sw + m * 4096 + jb;
#pragma unroll
        for (int k4 = 0; k4 < 16; k4++) {
            float4 v = __ldg(&ip[k4]);
            const float* wr = wm + (k4 * 4) * 64;
#pragma unroll
            for (int jj = 0; jj < 16; jj++) acc[jj] += v.x * wr[jj];
#pragma unroll
            for (int jj = 0; jj < 16; jj++) acc[jj] += v.y * wr[64 + jj];
#pragma unroll
            for (int jj = 0; jj < 16; jj++) acc[jj] += v.z * wr[128 + jj];
#pragma unroll
            for (int jj = 0; jj < 16; jj++) acc[jj] += v.w * wr[192 + jj];
        }
    }
    float* op = g_bufC + node * 64 + jb;
#pragma unroll
    for (int q = 0; q < 4; q++) {
        float4 o;
        o.x = fmaxf(acc[q * 4 + 0], 0.f);
        o.y = fmaxf(acc[q * 4 + 1], 0.f);
        o.z = fmaxf(acc[q * 4 + 2], 0.f);
        o.w = fmaxf(acc[q * 4 + 3], 0.f);
        ((float4*)op)[q] = o;
    }
}

// ---------------- dropout: JAX partitionable threefry, key(42) ---------------
// per element i: ctr64 = i -> (hi,lo) = (0, i); bits = o0 ^ o1; u < 0.5 keeps.
__global__ void dropout_kernel(int total) {
    int i = blockIdx.x * blockDim.x + threadIdx.x;
    if (i >= total) return;
    unsigned o0, o1;
    tf20(0u, 42u, 0u, (unsigned)i, o0, o1);
    unsigned bits = o0 ^ o1;
    float u = tf_uniform(bits);
    float a = g_bufC[i];
    g_bufC[i] = (u < 0.5f) ? 2.0f * a : 0.0f;
}

// ---------------- GEMM2 -------------------------------------------------------
__global__ void gemm2_kernel(const float* __restrict__ W,
                             const float* __restrict__ b,
                             float* __restrict__ out, int n) {
    __shared__ float sw[3 * 64 * 32];
    for (int i = threadIdx.x; i < 3 * 64 * 32 / 4; i += 256)
        ((float4*)sw)[i] = ((const float4*)W)[i];
    __syncthreads();

    int node = blockIdx.x * 128 + (threadIdx.x >> 1);
    int jb   = (threadIdx.x & 1) * 16;
    bool valid = (node < n);
    int nd = valid ? node : 0;

    float acc[16];
#pragma unroll
    for (int j = 0; j < 16; j++) acc[j] = __ldg(&b[jb + j]);

    const float* ins[3] = { g_bufC + nd * 64, g_bufA + nd * 64, g_bufB + nd * 64 };
#pragma unroll
    for (int m = 0; m < 3; m++) {
        const float4* ip = (const float4*)ins[m];
        const float* wm = sw + m * 2048 + jb;
#pragma unroll
        for (int k4 = 0; k4 < 16; k4++) {
            float4 v = __ldg(&ip[k4]);
            const float* wr = wm + (k4 * 4) * 32;
#pragma unroll
            for (int jj = 0; jj < 16; jj++) acc[jj] += v.x * wr[jj];
#pragma unroll
            for (int jj = 0; jj < 16; jj++) acc[jj] += v.y * wr[32 + jj];
#pragma unroll
            for (int jj = 0; jj < 16; jj++) acc[jj] += v.z * wr[64 + jj];
#pragma unroll
            for (int jj = 0; jj < 16; jj++) acc[jj] += v.w * wr[96 + jj];
        }
    }
    float mx = acc[0];
#pragma unroll
    for (int jj = 1; jj < 16; jj++) mx = fmaxf(mx, acc[jj]);
    float omx = __shfl_xor_sync(0xffffffffu, mx, 1);
    float M = fmaxf(mx, omx);
    float s = 0.f;
#pragma unroll
    for (int jj = 0; jj < 16; jj++) s += expf(acc[jj] - M);
    s += __shfl_xor_sync(0xffffffffu, s, 1);
    float lse = M + logf(s);
    if (valid) {
        float* op = out + node * 32 + jb;
#pragma unroll
        for (int q = 0; q < 4; q++) {
            float4 o;
            o.x = acc[q * 4 + 0] - lse;
            o.y = acc[q * 4 + 1] - lse;
            o.z = acc[q * 4 + 2] - lse;
            o.w = acc[q * 4 + 3] - lse;
            ((float4*)op)[q] = o;
        }
    }
}

// ---------------- launch ------------------------------------------------------
extern "C" void kernel_launch(void* const* d_in, const int* in_sizes, int n_in,
                              void* d_out, int out_size) {
    const float* x  = (const float*)d_in[0];
    const void*  ei = d_in[1];
    const float* W1 = (const float*)d_in[2];
    const float* b1 = (const float*)d_in[3];
    const float* W2 = (const float*)d_in[4];
    const float* b2 = (const float*)d_in[5];
    float* out = (float*)d_out;

    int n = in_sizes[0] / FIN;       // 100000
    int E = in_sizes[1] / 2;         // 1600000

    const int T = 256;
    int gN  = (n + T - 1) / T;
    int gE  = (E + T - 1) / T;
    int gW  = (n * 32 + T - 1) / T;
    int gG1 = (n + 63) / 64;
    int gG2 = (n + 127) / 128;
    int total = n * HID;
    int gD  = (total + T - 1) / T;

    detect_kernel<<<1, 32>>>((const unsigned*)ei);
    zero_deg_kernel<<<gN, T>>>(n);
    deg_hist_kernel<<<gE, T>>>(ei, E);
    scan_kernel<<<1, 1024>>>(n);
    dinv_kernel<<<gN, T>>>(n);
    scatter_kernel<<<gE, T>>>(ei, E);

    spmm_kernel<<<gW, T>>>(x, -1, 0, nullptr, -2, 0, n);
    spmm_kernel<<<gW, T>>>(nullptr, 0, 1, x, -1, 1, n);
    gemm1_kernel<<<gG1, T>>>(x, W1, b1, n);
    dropout_kernel<<<gD, T>>>(total);

    spmm_kernel<<<gW, T>>>(nullptr, 2, 0, nullptr, -2, 0, n);
    spmm_kernel<<<gW, T>>>(nullptr, 0, 1, nullptr, 2, 1, n);
    gemm2_kernel<<<gG2, T>>>(W2, b2, out, n);
}

// round 8
// speedup vs baseline: 1.9809x; 1.9809x over previous
#include <cuda_runtime.h>

// Problem constants
#define MAXN 100000
#define MAXE 1600000
#define FIN 64
#define HID 64
#define NCLS 32
#define SCAN_B 512
#define MAXBLK 256   // max scan blocks (MAXN/SCAN_B = 196)

// ---------------- scratch (static device globals; no allocation) -------------
__device__ int   g_is64;
__device__ int   g_deg[MAXN];
__device__ int   g_rowtmp[MAXN];
__device__ int   g_bsum[MAXBLK];
__device__ int   g_boff[MAXBLK];
__device__ int   g_rowptr[MAXN + 1];
__device__ int   g_cursor[MAXN];
__device__ float g_dinv[MAXN];
__device__ int   g_csrcol[MAXE];
__device__ float g_csrw[MAXE];
__device__ float g_bufA[MAXN * 64];
__device__ float g_bufB[MAXN * 64];
__device__ float g_bufC[MAXN * 64];

// resolve scratch-buffer selector inside device code (no host symbol lookup)
__device__ __forceinline__ float* selbuf(int s) {
    return (s == 0) ? g_bufA : (s == 1) ? g_bufB : g_bufC;
}

// read edge-index element e (element space of the TRUE dtype)
__device__ __forceinline__ int edge_at(const void* ei, int e) {
    if (g_is64) return (int)((const long long*)ei)[e];
    return ((const int*)ei)[e];
}

// ---------------- threefry2x32 (20 rounds) -----------------------------------
__device__ __forceinline__ unsigned rotl32(unsigned x, int d) {
    return (x << d) | (x >> (32 - d));
}

__device__ __forceinline__ void tf20(unsigned k0, unsigned k1,
                                     unsigned c0, unsigned c1,
                                     unsigned& o0, unsigned& o1) {
    unsigned ks0 = k0, ks1 = k1, ks2 = 0x1BD11BDAu ^ k0 ^ k1;
    unsigned x0 = c0 + ks0, x1 = c1 + ks1;
#define TFR(r) { x0 += x1; x1 = rotl32(x1, (r)); x1 ^= x0; }
    TFR(13) TFR(15) TFR(26) TFR(6)
    x0 += ks1; x1 += ks2 + 1u;
    TFR(17) TFR(29) TFR(16) TFR(24)
    x0 += ks2; x1 += ks0 + 2u;
    TFR(13) TFR(15) TFR(26) TFR(6)
    x0 += ks0; x1 += ks1 + 3u;
    TFR(17) TFR(29) TFR(16) TFR(24)
    x0 += ks1; x1 += ks2 + 4u;
    TFR(13) TFR(15) TFR(26) TFR(6)
    x0 += ks2; x1 += ks0 + 5u;
#undef TFR
    o0 = x0; o1 = x1;
}

__device__ __forceinline__ float tf_uniform(unsigned bits) {
    return __uint_as_float((bits >> 9) | 0x3F800000u) - 1.0f;
}

// ---------------- dtype probe -------------------------------------------------
__global__ void detect_kernel(const unsigned* __restrict__ w) {
    if (threadIdx.x == 0) {
        int is64 = 1;
        #pragma unroll
        for (int k = 0; k < 8; k++)
            if (w[2 * k + 1] != 0u) is64 = 0;
        g_is64 = is64;
    }
}

// ---------------- setup kernels ----------------------------------------------
__global__ void zero_deg_kernel(int n) {
    int i = blockIdx.x * blockDim.x + threadIdx.x;
    if (i < n) g_deg[i] = 0;
}

__global__ void deg_hist_kernel(const void* __restrict__ ei, int E) {
    int e = blockIdx.x * blockDim.x + threadIdx.x;
    if (e < E) {
        int r = edge_at(ei, e);
        atomicAdd(&g_deg[r], 1);
    }
}

// ---- 3-phase device-wide exclusive scan of g_deg ----------------------------
// phase 1: per-block inclusive scan (SCAN_B elements/block); write per-element
//          exclusive value to g_rowtmp, block total to g_bsum
__global__ void scan_local_kernel(int n) {
    __shared__ int sh[SCAN_B];
    int t = threadIdx.x;
    int i = blockIdx.x * SCAN_B + t;
    int v = (i < n) ? g_deg[i] : 0;
    sh[t] = v;
    __syncthreads();
    for (int off = 1; off < SCAN_B; off <<= 1) {
        int u = (t >= off) ? sh[t - off] : 0;
        __syncthreads();
        if (t >= off) sh[t] += u;
        __syncthreads();
    }
    if (i < n) g_rowtmp[i] = sh[t] - v;          // exclusive within block
    if (t == SCAN_B - 1) g_bsum[blockIdx.x] = sh[t];
}

// phase 2: single small block scans the block sums (exclusive)
__global__ void scan_bsums_kernel(int nb) {
    __shared__ int sh[MAXBLK];
    int t = threadIdx.x;
    int v = (t < nb) ? g_bsum[t] : 0;
    sh[t] = v;
    __syncthreads();
    for (int off = 1; off < MAXBLK; off <<= 1) {
        int u = (t >= off) ? sh[t - off] : 0;
        __syncthreads();
        if (t >= off) sh[t] += u;
        __syncthreads();
    }
    if (t < nb) g_boff[t] = sh[t] - v;           // exclusive block offset
}

// phase 3: add block offsets, produce rowptr + cursor; rowptr[n] = E
__global__ void scan_final_kernel(int n, int E) {
    int i = blockIdx.x * blockDim.x + threadIdx.x;
    if (i < n) {
        int v = g_rowtmp[i] + g_boff[i / SCAN_B];
        g_rowptr[i] = v;
        g_cursor[i] = v;
    }
    if (i == 0) g_rowptr[n] = E;
}

__global__ void dinv_kernel(int n) {
    int i = blockIdx.x * blockDim.x + threadIdx.x;
    if (i < n) {
        int d = g_deg[i];
        g_dinv[i] = (d > 0) ? rsqrtf((float)d) : 0.0f;
    }
}

__global__ void scatter_kernel(const void* __restrict__ ei, int E) {
    int e = blockIdx.x * blockDim.x + threadIdx.x;
    if (e < E) {
        int r = edge_at(ei, e);
        int c = edge_at(ei, E + e);
        int pos = atomicAdd(&g_cursor[r], 1);
        g_csrcol[pos] = c;
        g_csrw[pos]   = -(g_dinv[r] * g_dinv[c]);
    }
}

// ---------------- SpMM --------------------------------------------------------
__global__ void spmm_kernel(const float* __restrict__ ext_src, int src_sel,
                            int dst_sel,
                            const float* __restrict__ ext_other, int other_sel,
                            int mode, int n) {
    const float* src = (src_sel < 0) ? ext_src : selbuf(src_sel);
    float*       dst = selbuf(dst_sel);
    int warp = (blockIdx.x * blockDim.x + threadIdx.x) >> 5;
    int lane = threadIdx.x & 31;
    if (warp >= n) return;
    int start = g_rowptr[warp];
    int end   = g_rowptr[warp + 1];
    const float2* s2 = (const float2*)src;
    float ax = 0.f, ay = 0.f;
    int e = start;
    for (; e + 1 < end; e += 2) {
        int   c0 = g_csrcol[e];
        int   c1 = g_csrcol[e + 1];
        float w0 = g_csrw[e];
        float w1 = g_csrw[e + 1];
        float2 v0 = __ldg(&s2[c0 * 32 + lane]);
        float2 v1 = __ldg(&s2[c1 * 32 + lane]);
        ax += w0 * v0.x + w1 * v1.x;
        ay += w0 * v0.y + w1 * v1.y;
    }
    if (e < end) {
        int c = g_csrcol[e];
        float w = g_csrw[e];
        float2 v = __ldg(&s2[c * 32 + lane]);
        ax += w * v.x;
        ay += w * v.y;
    }
    if (mode) {
        const float* oth = (other_sel < 0) ? ext_other : selbuf(other_sel);
        float2 o = ((const float2*)oth)[warp * 32 + lane];
        ax = 2.0f * ax - o.x;
        ay = 2.0f * ay - o.y;
    }
    ((float2*)dst)[warp * 32 + lane] = make_float2(ax, ay);
}

// ---------------- GEMM1 -------------------------------------------------------
__global__ void gemm1_kernel(const float* __restrict__ x,
                             const float* __restrict__ W,
                             const float* __restrict__ b, int n) {
    __shared__ float sw[3 * 64 * 64];
    for (int i = threadIdx.x; i < 3 * 64 * 64 / 4; i += 256)
        ((float4*)sw)[i] = ((const float4*)W)[i];
    __syncthreads();

    int node = blockIdx.x * 64 + (threadIdx.x >> 2);
    int jb   = (threadIdx.x & 3) * 16;
    if (node >= n) return;

    float acc[16];
#pragma unroll
    for (int j = 0; j < 16; j++) acc[j] = __ldg(&b[jb + j]);

    const float* ins[3] = { x + node * 64, g_bufA + node * 64, g_bufB + node * 64 };
#pragma unroll
    for (int m = 0; m < 3; m++) {
        const float4* ip = (const float4*)ins[m];
        const float* wm = sw + m * 4096 + jb;
#pragma unroll
        for (int k4 = 0; k4 < 16; k4++) {
            float4 v = __ldg(&ip[k4]);
            const float* wr = wm + (k4 * 4) * 64;
#pragma unroll
            for (int jj = 0; jj < 16; jj++) acc[jj] += v.x * wr[jj];
#pragma unroll
            for (int jj = 0; jj < 16; jj++) acc[jj] += v.y * wr[64 + jj];
#pragma unroll
            for (int jj = 0; jj < 16; jj++) acc[jj] += v.z * wr[128 + jj];
#pragma unroll
            for (int jj = 0; jj < 16; jj++) acc[jj] += v.w * wr[192 + jj];
        }
    }
    float* op = g_bufC + node * 64 + jb;
#pragma unroll
    for (int q = 0; q < 4; q++) {
        float4 o;
        o.x = fmaxf(acc[q * 4 + 0], 0.f);
        o.y = fmaxf(acc[q * 4 + 1], 0.f);
        o.z = fmaxf(acc[q * 4 + 2], 0.f);
        o.w = fmaxf(acc[q * 4 + 3], 0.f);
        ((float4*)op)[q] = o;
    }
}

// ---------------- dropout: JAX partitionable threefry, key(42) ---------------
__global__ void dropout_kernel(int total) {
    int i = blockIdx.x * blockDim.x + threadIdx.x;
    if (i >= total) return;
    unsigned o0, o1;
    tf20(0u, 42u, 0u, (unsigned)i, o0, o1);
    unsigned bits = o0 ^ o1;
    float u = tf_uniform(bits);
    float a = g_bufC[i];
    g_bufC[i] = (u < 0.5f) ? 2.0f * a : 0.0f;
}

// ---------------- GEMM2 -------------------------------------------------------
__global__ void gemm2_kernel(const float* __restrict__ W,
                             const float* __restrict__ b,
                             float* __restrict__ out, int n) {
    __shared__ float sw[3 * 64 * 32];
    for (int i = threadIdx.x; i < 3 * 64 * 32 / 4; i += 256)
        ((float4*)sw)[i] = ((const float4*)W)[i];
    __syncthreads();

    int node = blockIdx.x * 128 + (threadIdx.x >> 1);
    int jb   = (threadIdx.x & 1) * 16;
    bool valid = (node < n);
    int nd = valid ? node : 0;

    float acc[16];
#pragma unroll
    for (int j = 0; j < 16; j++) acc[j] = __ldg(&b[jb + j]);

    const float* ins[3] = { g_bufC + nd * 64, g_bufA + nd * 64, g_bufB + nd * 64 };
#pragma unroll
    for (int m = 0; m < 3; m++) {
        const float4* ip = (const float4*)ins[m];
        const float* wm = sw + m * 2048 + jb;
#pragma unroll
        for (int k4 = 0; k4 < 16; k4++) {
            float4 v = __ldg(&ip[k4]);
            const float* wr = wm + (k4 * 4) * 32;
#pragma unroll
            for (int jj = 0; jj < 16; jj++) acc[jj] += v.x * wr[jj];
#pragma unroll
            for (int jj = 0; jj < 16; jj++) acc[jj] += v.y * wr[32 + jj];
#pragma unroll
            for (int jj = 0; jj < 16; jj++) acc[jj] += v.z * wr[64 + jj];
#pragma unroll
            for (int jj = 0; jj < 16; jj++) acc[jj] += v.w * wr[96 + jj];
        }
    }
    float mx = acc[0];
#pragma unroll
    for (int jj = 1; jj < 16; jj++) mx = fmaxf(mx, acc[jj]);
    float omx = __shfl_xor_sync(0xffffffffu, mx, 1);
    float M = fmaxf(mx, omx);
    float s = 0.f;
#pragma unroll
    for (int jj = 0; jj < 16; jj++) s += expf(acc[jj] - M);
    s += __shfl_xor_sync(0xffffffffu, s, 1);
    float lse = M + logf(s);
    if (valid) {
        float* op = out + node * 32 + jb;
#pragma unroll
        for (int q = 0; q < 4; q++) {
            float4 o;
            o.x = acc[q * 4 + 0] - lse;
            o.y = acc[q * 4 + 1] - lse;
            o.z = acc[q * 4 + 2] - lse;
            o.w = acc[q * 4 + 3] - lse;
            ((float4*)op)[q] = o;
        }
    }
}

// ---------------- launch ------------------------------------------------------
extern "C" void kernel_launch(void* const* d_in, const int* in_sizes, int n_in,
                              void* d_out, int out_size) {
    const float* x  = (const float*)d_in[0];
    const void*  ei = d_in[1];
    const float* W1 = (const float*)d_in[2];
    const float* b1 = (const float*)d_in[3];
    const float* W2 = (const float*)d_in[4];
    const float* b2 = (const float*)d_in[5];
    float* out = (float*)d_out;

    int n = in_sizes[0] / FIN;       // 100000
    int E = in_sizes[1] / 2;         // 1600000

    const int T = 256;
    int gN  = (n + T - 1) / T;
    int gE  = (E + T - 1) / T;
    int gW  = (n * 32 + T - 1) / T;
    int gG1 = (n + 63) / 64;
    int gG2 = (n + 127) / 128;
    int total = n * HID;
    int gD  = (total + T - 1) / T;
    int nb  = (n + SCAN_B - 1) / SCAN_B;   // scan blocks (196)

    detect_kernel<<<1, 32>>>((const unsigned*)ei);
    zero_deg_kernel<<<gN, T>>>(n);
    deg_hist_kernel<<<gE, T>>>(ei, E);
    scan_local_kernel<<<nb, SCAN_B>>>(n);
    scan_bsums_kernel<<<1, MAXBLK>>>(nb);
    scan_final_kernel<<<gN, T>>>(n, E);
    dinv_kernel<<<gN, T>>>(n);
    scatter_kernel<<<gE, T>>>(ei, E);

    spmm_kernel<<<gW, T>>>(x, -1, 0, nullptr, -2, 0, n);
    spmm_kernel<<<gW, T>>>(nullptr, 0, 1, x, -1, 1, n);
    gemm1_kernel<<<gG1, T>>>(x, W1, b1, n);
    dropout_kernel<<<gD, T>>>(total);

    spmm_kernel<<<gW, T>>>(nullptr, 2, 0, nullptr, -2, 0, n);
    spmm_kernel<<<gW, T>>>(nullptr, 0, 1, nullptr, 2, 1, n);
    gemm2_kernel<<<gG2, T>>>(W2, b2, out, n);
}

// round 9
// speedup vs baseline: 2.4935x; 1.2588x over previous
#include <cuda_runtime.h>

// Problem constants
#define MAXN 100000
#define MAXE 1600000
#define FIN 64
#define HID 64
#define NCLS 32
#define SCAN_B 512
#define MAXBLK 256   // max scan blocks (MAXN/SCAN_B = 196)

// ---------------- scratch (static device globals; no allocation) -------------
__device__ int   g_is64;
__device__ int   g_deg[MAXN];
__device__ int   g_rowtmp[MAXN];
__device__ int   g_bsum[MAXBLK];
__device__ int   g_boff[MAXBLK];
__device__ int   g_rowptr[MAXN + 1];
__device__ int   g_cursor[MAXN];
__device__ float g_dinv[MAXN];
__device__ int2  g_csr[MAXE];          // {col, float_as_int(weight)}
__device__ float g_bufA[MAXN * 64];
__device__ float g_bufB[MAXN * 64];
__device__ float g_bufC[MAXN * 64];

__device__ __forceinline__ float* selbuf(int s) {
    return (s == 0) ? g_bufA : (s == 1) ? g_bufB : g_bufC;
}

__device__ __forceinline__ int edge_at(const void* ei, int e) {
    if (g_is64) return (int)((const long long*)ei)[e];
    return ((const int*)ei)[e];
}

// ---------------- threefry2x32 (20 rounds) -----------------------------------
__device__ __forceinline__ unsigned rotl32(unsigned x, int d) {
    return (x << d) | (x >> (32 - d));
}

__device__ __forceinline__ void tf20(unsigned k0, unsigned k1,
                                     unsigned c0, unsigned c1,
                                     unsigned& o0, unsigned& o1) {
    unsigned ks0 = k0, ks1 = k1, ks2 = 0x1BD11BDAu ^ k0 ^ k1;
    unsigned x0 = c0 + ks0, x1 = c1 + ks1;
#define TFR(r) { x0 += x1; x1 = rotl32(x1, (r)); x1 ^= x0; }
    TFR(13) TFR(15) TFR(26) TFR(6)
    x0 += ks1; x1 += ks2 + 1u;
    TFR(17) TFR(29) TFR(16) TFR(24)
    x0 += ks2; x1 += ks0 + 2u;
    TFR(13) TFR(15) TFR(26) TFR(6)
    x0 += ks0; x1 += ks1 + 3u;
    TFR(17) TFR(29) TFR(16) TFR(24)
    x0 += ks1; x1 += ks2 + 4u;
    TFR(13) TFR(15) TFR(26) TFR(6)
    x0 += ks2; x1 += ks0 + 5u;
#undef TFR
    o0 = x0; o1 = x1;
}

// dropout keep decision for flat element index i (JAX partitionable threefry)
__device__ __forceinline__ bool keep_elem(int i) {
    unsigned o0, o1;
    tf20(0u, 42u, 0u, (unsigned)i, o0, o1);
    unsigned bits = o0 ^ o1;
    float u = __uint_as_float((bits >> 9) | 0x3F800000u) - 1.0f;
    return u < 0.5f;
}

// ---------------- setup kernels ----------------------------------------------
// zero deg + fold in the dtype probe (block 0, thread 0)
__global__ void zero_detect_kernel(const unsigned* __restrict__ w, int n) {
    int i = blockIdx.x * blockDim.x + threadIdx.x;
    if (i < n) g_deg[i] = 0;
    if (i == 0) {
        int is64 = 1;
        #pragma unroll
        for (int k = 0; k < 8; k++)
            if (w[2 * k + 1] != 0u) is64 = 0;
        g_is64 = is64;
    }
}

__global__ void deg_hist_kernel(const void* __restrict__ ei, int E) {
    int e = blockIdx.x * blockDim.x + threadIdx.x;
    if (e < E) {
        int r = edge_at(ei, e);
        atomicAdd(&g_deg[r], 1);
    }
}

// ---- 3-phase device-wide exclusive scan of g_deg ----------------------------
__global__ void scan_local_kernel(int n) {
    __shared__ int sh[SCAN_B];
    int t = threadIdx.x;
    int i = blockIdx.x * SCAN_B + t;
    int v = (i < n) ? g_deg[i] : 0;
    sh[t] = v;
    __syncthreads();
    for (int off = 1; off < SCAN_B; off <<= 1) {
        int u = (t >= off) ? sh[t - off] : 0;
        __syncthreads();
        if (t >= off) sh[t] += u;
        __syncthreads();
    }
    if (i < n) g_rowtmp[i] = sh[t] - v;
    if (t == SCAN_B - 1) g_bsum[blockIdx.x] = sh[t];
}

__global__ void scan_bsums_kernel(int nb) {
    __shared__ int sh[MAXBLK];
    int t = threadIdx.x;
    int v = (t < nb) ? g_bsum[t] : 0;
    sh[t] = v;
    __syncthreads();
    for (int off = 1; off < MAXBLK; off <<= 1) {
        int u = (t >= off) ? sh[t - off] : 0;
        __syncthreads();
        if (t >= off) sh[t] += u;
        __syncthreads();
    }
    if (t < nb) g_boff[t] = sh[t] - v;
}

// phase 3 + dinv fused
__global__ void scan_final_kernel(int n, int E) {
    int i = blockIdx.x * blockDim.x + threadIdx.x;
    if (i < n) {
        int v = g_rowtmp[i] + g_boff[i / SCAN_B];
        g_rowptr[i] = v;
        g_cursor[i] = v;
        int d = g_deg[i];
        g_dinv[i] = (d > 0) ? rsqrtf((float)d) : 0.0f;
    }
    if (i == 0) g_rowptr[n] = E;
}

__global__ void scatter_kernel(const void* __restrict__ ei, int E) {
    int e = blockIdx.x * blockDim.x + threadIdx.x;
    if (e < E) {
        int r = edge_at(ei, e);
        int c = edge_at(ei, E + e);
        int pos = atomicAdd(&g_cursor[r], 1);
        float w = -(g_dinv[r] * g_dinv[c]);
        g_csr[pos] = make_int2(c, __float_as_int(w));
    }
}

// ---------------- SpMM v2 -----------------------------------------------------
// warp per node; cooperative edge-metadata load + shfl broadcast; 4-deep gathers
__global__ void spmm_kernel(const float* __restrict__ ext_src, int src_sel,
                            int dst_sel,
                            const float* __restrict__ ext_other, int other_sel,
                            int mode, int n) {
    const float* src = (src_sel < 0) ? ext_src : selbuf(src_sel);
    float*       dst = selbuf(dst_sel);
    int node = (blockIdx.x * blockDim.x + threadIdx.x) >> 5;
    int lane = threadIdx.x & 31;
    if (node >= n) return;
    int start = g_rowptr[node];
    int end   = g_rowptr[node + 1];
    const float2* s2 = (const float2*)src;
    float ax = 0.f, ay = 0.f;

    for (int base = start; base < end; base += 32) {
        int idx = base + lane;
        int2 ce = make_int2(0, 0);
        if (idx < end) ce = g_csr[idx];
        int cnt = min(32, end - base);
        int j = 0;
        for (; j + 4 <= cnt; j += 4) {
            int   c0 = __shfl_sync(0xffffffffu, ce.x, j);
            int   c1 = __shfl_sync(0xffffffffu, ce.x, j + 1);
            int   c2 = __shfl_sync(0xffffffffu, ce.x, j + 2);
            int   c3 = __shfl_sync(0xffffffffu, ce.x, j + 3);
            float w0 = __int_as_float(__shfl_sync(0xffffffffu, ce.y, j));
            float w1 = __int_as_float(__shfl_sync(0xffffffffu, ce.y, j + 1));
            float w2 = __int_as_float(__shfl_sync(0xffffffffu, ce.y, j + 2));
            float w3 = __int_as_float(__shfl_sync(0xffffffffu, ce.y, j + 3));
            float2 v0 = __ldg(&s2[c0 * 32 + lane]);
            float2 v1 = __ldg(&s2[c1 * 32 + lane]);
            float2 v2 = __ldg(&s2[c2 * 32 + lane]);
            float2 v3 = __ldg(&s2[c3 * 32 + lane]);
            ax += w0 * v0.x; ay += w0 * v0.y;
            ax += w1 * v1.x; ay += w1 * v1.y;
            ax += w2 * v2.x; ay += w2 * v2.y;
            ax += w3 * v3.x; ay += w3 * v3.y;
        }
        for (; j < cnt; j++) {
            int   c = __shfl_sync(0xffffffffu, ce.x, j);
            float w = __int_as_float(__shfl_sync(0xffffffffu, ce.y, j));
            float2 v = __ldg(&s2[c * 32 + lane]);
            ax += w * v.x; ay += w * v.y;
        }
    }
    if (mode) {
        const float* oth = (other_sel < 0) ? ext_other : selbuf(other_sel);
        float2 o = ((const float2*)oth)[node * 32 + lane];
        ax = 2.0f * ax - o.x;
        ay = 2.0f * ay - o.y;
    }
    ((float2*)dst)[node * 32 + lane] = make_float2(ax, ay);
}

// ---------------- GEMM1: h = dropout(relu(x@W0 + A@W1 + B@W2 + b)) -----------
// 256 threads; thread handles 2 nodes (halves shared-weight LDS per FMA);
// 128 nodes/block, 4 threads per node-column group (16 outputs each)
__global__ void __launch_bounds__(256) gemm1_kernel(
        const float* __restrict__ x,
        const float* __restrict__ W,
        const float* __restrict__ b, int n) {
    __shared__ float sw[3 * 64 * 64];  // 48KB
    for (int i = threadIdx.x; i < 3 * 64 * 64 / 4; i += 256)
        ((float4*)sw)[i] = ((const float4*)W)[i];
    __syncthreads();

    int local = threadIdx.x >> 2;              // 0..63
    int jb    = (threadIdx.x & 3) * 16;
    int node0 = blockIdx.x * 128 + local;
    int node1 = node0 + 64;
    if (node0 >= n) return;
    bool v1 = (node1 < n);
    int nd1 = v1 ? node1 : node0;

    float acc0[16], acc1[16];
#pragma unroll
    for (int j = 0; j < 16; j++) { acc0[j] = __ldg(&b[jb + j]); acc1[j] = acc0[j]; }

    const float* in0[3] = { x + node0 * 64, g_bufA + node0 * 64, g_bufB + node0 * 64 };
    const float* in1[3] = { x + nd1 * 64,   g_bufA + nd1 * 64,   g_bufB + nd1 * 64 };
#pragma unroll
    for (int m = 0; m < 3; m++) {
        const float4* ip0 = (const float4*)in0[m];
        const float4* ip1 = (const float4*)in1[m];
        const float* wm = sw + m * 4096 + jb;
#pragma unroll
        for (int k4 = 0; k4 < 16; k4++) {
            float4 a4 = __ldg(&ip0[k4]);
            float4 b4 = __ldg(&ip1[k4]);
            const float* wr = wm + (k4 * 4) * 64;
#pragma unroll
            for (int c = 0; c < 4; c++) {
                float av = ((const float*)&a4)[c];
                float bv = ((const float*)&b4)[c];
                const float* wrow = wr + c * 64;
#pragma unroll
                for (int jj = 0; jj < 16; jj++) {
                    float wv = wrow[jj];
                    acc0[jj] += av * wv;
                    acc1[jj] += bv * wv;
                }
            }
        }
    }
    // relu + dropout fused epilogue
    {
        float* op = g_bufC + node0 * 64 + jb;
        int ib = node0 * 64 + jb;
#pragma unroll
        for (int q = 0; q < 4; q++) {
            float4 o;
            o.x = keep_elem(ib + q * 4 + 0) ? 2.0f * fmaxf(acc0[q * 4 + 0], 0.f) : 0.f;
            o.y = keep_elem(ib + q * 4 + 1) ? 2.0f * fmaxf(acc0[q * 4 + 1], 0.f) : 0.f;
            o.z = keep_elem(ib + q * 4 + 2) ? 2.0f * fmaxf(acc0[q * 4 + 2], 0.f) : 0.f;
            o.w = keep_elem(ib + q * 4 + 3) ? 2.0f * fmaxf(acc0[q * 4 + 3], 0.f) : 0.f;
            ((float4*)op)[q] = o;
        }
    }
    if (v1) {
        float* op = g_bufC + node1 * 64 + jb;
        int ib = node1 * 64 + jb;
#pragma unroll
        for (int q = 0; q < 4; q++) {
            float4 o;
            o.x = keep_elem(ib + q * 4 + 0) ? 2.0f * fmaxf(acc1[q * 4 + 0], 0.f) : 0.f;
            o.y = keep_elem(ib + q * 4 + 1) ? 2.0f * fmaxf(acc1[q * 4 + 1], 0.f) : 0.f;
            o.z = keep_elem(ib + q * 4 + 2) ? 2.0f * fmaxf(acc1[q * 4 + 2], 0.f) : 0.f;
            o.w = keep_elem(ib + q * 4 + 3) ? 2.0f * fmaxf(acc1[q * 4 + 3], 0.f) : 0.f;
            ((float4*)op)[q] = o;
        }
    }
}

// ---------------- GEMM2: out = log_softmax(h@W0 + A@W1 + B@W2 + b) -----------
// 256 threads; thread handles 2 nodes; 256 nodes/block, 2 threads/node
__global__ void __launch_bounds__(256) gemm2_kernel(
        const float* __restrict__ W,
        const float* __restrict__ b,
        float* __restrict__ out, int n) {
    __shared__ float sw[3 * 64 * 32];  // 24KB
    for (int i = threadIdx.x; i < 3 * 64 * 32 / 4; i += 256)
        ((float4*)sw)[i] = ((const float4*)W)[i];
    __syncthreads();

    int local = threadIdx.x >> 1;              // 0..127
    int jb    = (threadIdx.x & 1) * 16;
    int node0 = blockIdx.x * 256 + local;
    int node1 = node0 + 128;
    bool v0 = (node0 < n);
    bool v1 = (node1 < n);
    int nd0 = v0 ? node0 : 0;
    int nd1 = v1 ? node1 : nd0;

    float acc0[16], acc1[16];
#pragma unroll
    for (int j = 0; j < 16; j++) { acc0[j] = __ldg(&b[jb + j]); acc1[j] = acc0[j]; }

    const float* in0[3] = { g_bufC + nd0 * 64, g_bufA + nd0 * 64, g_bufB + nd0 * 64 };
    const float* in1[3] = { g_bufC + nd1 * 64, g_bufA + nd1 * 64, g_bufB + nd1 * 64 };
#pragma unroll
    for (int m = 0; m < 3; m++) {
        const float4* ip0 = (const float4*)in0[m];
        const float4* ip1 = (const float4*)in1[m];
        const float* wm = sw + m * 2048 + jb;
#pragma unroll
        for (int k4 = 0; k4 < 16; k4++) {
            float4 a4 = __ldg(&ip0[k4]);
            float4 b4 = __ldg(&ip1[k4]);
            const float* wr = wm + (k4 * 4) * 32;
#pragma unroll
            for (int c = 0; c < 4; c++) {
                float av = ((const float*)&a4)[c];
                float bv = ((const float*)&b4)[c];
                const float* wrow = wr + c * 32;
#pragma unroll
                for (int jj = 0; jj < 16; jj++) {
                    float wv = wrow[jj];
                    acc0[jj] += av * wv;
                    acc1[jj] += bv * wv;
                }
            }
        }
    }
    // log_softmax per node; threads (t, t^1) share the two class halves
    float mx0 = acc0[0], mx1 = acc1[0];
#pragma unroll
    for (int jj = 1; jj < 16; jj++) { mx0 = fmaxf(mx0, acc0[jj]); mx1 = fmaxf(mx1, acc1[jj]); }
    float M0 = fmaxf(mx0, __shfl_xor_sync(0xffffffffu, mx0, 1));
    float M1 = fmaxf(mx1, __shfl_xor_sync(0xffffffffu, mx1, 1));
    float s0 = 0.f, s1 = 0.f;
#pragma unroll
    for (int jj = 0; jj < 16; jj++) { s0 += expf(acc0[jj] - M0); s1 += expf(acc1[jj] - M1); }
    s0 += __shfl_xor_sync(0xffffffffu, s0, 1);
    s1 += __shfl_xor_sync(0xffffffffu, s1, 1);
    float lse0 = M0 + logf(s0);
    float lse1 = M1 + logf(s1);
    if (v0) {
        float* op = out + node0 * 32 + jb;
#pragma unroll
        for (int q = 0; q < 4; q++) {
            float4 o;
            o.x = acc0[q * 4 + 0] - lse0; o.y = acc0[q * 4 + 1] - lse0;
            o.z = acc0[q * 4 + 2] - lse0; o.w = acc0[q * 4 + 3] - lse0;
            ((float4*)op)[q] = o;
        }
    }
    if (v1) {
        float* op = out + node1 * 32 + jb;
#pragma unroll
        for (int q = 0; q < 4; q++) {
            float4 o;
            o.x = acc1[q * 4 + 0] - lse1; o.y = acc1[q * 4 + 1] - lse1;
            o.z = acc1[q * 4 + 2] - lse1; o.w = acc1[q * 4 + 3] - lse1;
            ((float4*)op)[q] = o;
        }
    }
}

// ---------------- launch ------------------------------------------------------
extern "C" void kernel_launch(void* const* d_in, const int* in_sizes, int n_in,
                              void* d_out, int out_size) {
    const float* x  = (const float*)d_in[0];
    const void*  ei = d_in[1];
    const float* W1 = (const float*)d_in[2];
    const float* b1 = (const float*)d_in[3];
    const float* W2 = (const float*)d_in[4];
    const float* b2 = (const float*)d_in[5];
    float* out = (float*)d_out;

    int n = in_sizes[0] / FIN;       // 100000
    int E = in_sizes[1] / 2;         // 1600000

    const int T = 256;
    int gN  = (n + T - 1) / T;
    int gE  = (E + T - 1) / T;
    int gW  = (n * 32 + T - 1) / T;
    int gG1 = (n + 127) / 128;
    int gG2 = (n + 255) / 256;
    int nb  = (n + SCAN_B - 1) / SCAN_B;

    zero_detect_kernel<<<gN, T>>>((const unsigned*)ei, n);
    deg_hist_kernel<<<gE, T>>>(ei, E);
    scan_local_kernel<<<nb, SCAN_B>>>(n);
    scan_bsums_kernel<<<1, MAXBLK>>>(nb);
    scan_final_kernel<<<gN, T>>>(n, E);
    scatter_kernel<<<gE, T>>>(ei, E);

    spmm_kernel<<<gW, T>>>(x, -1, 0, nullptr, -2, 0, n);
    spmm_kernel<<<gW, T>>>(nullptr, 0, 1, x, -1, 1, n);
    gemm1_kernel<<<gG1, T>>>(x, W1, b1, n);

    spmm_kernel<<<gW, T>>>(nullptr, 2, 0, nullptr, -2, 0, n);
    spmm_kernel<<<gW, T>>>(nullptr, 0, 1, nullptr, 2, 1, n);
    gemm2_kernel<<<gG2, T>>>(W2, b2, out, n);
}